// round 16
// baseline (speedup 1.0000x reference)
#include <cuda_runtime.h>
#include <cuda_bf16.h>
#include <math.h>
#include <stdint.h>

typedef unsigned long long ull;

#define NBLK 128
#define NSTEP 50
#define NOUT 50257

// ---------------- device scratch (no allocs allowed) ----------------
__device__ float g_X[64 * 1024];      // padded inputs (rows 50..63 zero)
__device__ float g_Gin[50 * 4096];    // W_ih @ x_t + b_ih + b_hh
__device__ float g_HS[64 * 1024];     // h_t history (rows 50..63 zero)
__device__ float g_h[2][1024];        // double-buffered hidden state
__device__ unsigned g_arrive;         // cumulative grid-barrier counter
__device__ __align__(16) unsigned g_Ah[64 * 512];  // A bf16-hi pairs (X or HS)
__device__ __align__(16) unsigned g_Al[64 * 512];  // A bf16-lo pairs

// ---------------- helpers ----------------
__device__ __forceinline__ ull pack2(float x, float y) {
    ull r;
    asm("mov.b64 %0, {%1, %2};" : "=l"(r) : "f"(x), "f"(y));
    return r;
}
__device__ __forceinline__ void ffma2(ull& d, ull a, ull b) {
    asm("fma.rn.f32x2 %0, %1, %2, %0;" : "+l"(d) : "l"(a), "l"(b));
}
__device__ __forceinline__ float sum2(ull a) {
    float2 v = *(float2*)&a;
    return v.x + v.y;
}
__device__ __forceinline__ void red_release_add1(unsigned* p) {
    asm volatile("red.release.gpu.global.add.u32 [%0], 1;" :: "l"(p) : "memory");
}
__device__ __forceinline__ unsigned ld_acquire(const unsigned* p) {
    unsigned v;
    asm volatile("ld.acquire.gpu.global.u32 %0, [%1];" : "=r"(v) : "l"(p) : "memory");
    return v;
}
__device__ __forceinline__ uint32_t smem_u32(const void* p) {
    uint32_t a;
    asm("{ .reg .u64 t; cvta.to.shared.u64 t, %1; cvt.u32.u64 %0, t; }"
        : "=r"(a) : "l"(p));
    return a;
}
// ldmatrix x4: four 8x8 b16 tiles (baseline PTX, sm_75+)
__device__ __forceinline__ void ldsm_x4(unsigned& r0, unsigned& r1, unsigned& r2,
                                        unsigned& r3, uint32_t addr) {
    asm volatile(
        "ldmatrix.sync.aligned.m8n8.x4.shared.b16 {%0,%1,%2,%3}, [%4];"
        : "=r"(r0), "=r"(r1), "=r"(r2), "=r"(r3) : "r"(addr));
}
// cp.async 16B with byte-size predicate (0 => zero-fill)
__device__ __forceinline__ void cp_async16(uint32_t dst, const void* src, unsigned sz) {
    asm volatile("cp.async.cg.shared.global [%0], [%1], 16, %2;"
                 :: "r"(dst), "l"(src), "r"(sz) : "memory");
}
__device__ __forceinline__ void cp_commit() {
    asm volatile("cp.async.commit_group;" ::: "memory");
}
__device__ __forceinline__ void cp_wait1() {
    asm volatile("cp.async.wait_group 1;" ::: "memory");
}

// bf16 hi/lo split of a float pair, packed little-endian (x=low half)
__device__ __forceinline__ void cvt_pair(float x, float y, unsigned& hi, unsigned& lo) {
    __nv_bfloat162 h = __floats2bfloat162_rn(x, y);
    float rx = x - __bfloat162float(h.x);
    float ry = y - __bfloat162float(h.y);
    __nv_bfloat162 l = __floats2bfloat162_rn(rx, ry);
    hi = *(unsigned*)&h;
    lo = *(unsigned*)&l;
}

// mma.sync m16n8k16 bf16 (baseline PTX, works on compute_100)
__device__ __forceinline__ void mma_bf16(float* d, const unsigned* a, const unsigned* b) {
    asm volatile(
        "mma.sync.aligned.m16n8k16.row.col.f32.bf16.bf16.f32 "
        "{%0,%1,%2,%3}, {%4,%5,%6,%7}, {%8,%9}, {%0,%1,%2,%3};"
        : "+f"(d[0]), "+f"(d[1]), "+f"(d[2]), "+f"(d[3])
        : "r"(a[0]), "r"(a[1]), "r"(a[2]), "r"(a[3]), "r"(b[0]), "r"(b[1]));
}

// ---------------- prep (R14): gather X rows, zero pads, init state ----------------
__global__ void prep_kernel(const int* __restrict__ sent,
                            const float* __restrict__ emb,
                            const float* __restrict__ h0) {
    int b = blockIdx.x;
    int tid = threadIdx.x;  // 256 threads, float4 each -> 1024 floats
    if (b < 64) {
        float4* dst = (float4*)(g_X + (size_t)b * 1024);
        if (b < 50) {
            int row = (b == 0) ? 1 : sent[b - 1];  // START_ID = 1
            const float4* src = (const float4*)(emb + (size_t)row * 1024);
            dst[tid] = src[tid];
        } else {
            float4 z = make_float4(0.f, 0.f, 0.f, 0.f);
            dst[tid] = z;
            ((float4*)(g_HS + (size_t)b * 1024))[tid] = z;  // zero MMA pad rows
        }
    } else {
        ((float4*)g_h[0])[tid] = ((const float4*)h0)[tid];
        if (tid == 0) g_arrive = 0u;
    }
}

// ---------------- split a fp32 [64][1024] matrix into packed bf16 hi/lo ----------------
__global__ void cvt_split_kernel(const float* __restrict__ src) {
    int i = blockIdx.x * 256 + threadIdx.x;  // over 32768 float2 pairs
    float2 v = ((const float2*)src)[i];
    unsigned hi, lo;
    cvt_pair(v.x, v.y, hi, lo);
    g_Ah[i] = hi;
    g_Al[i] = lo;
}

// ---------------- R14-proven GEMM (scalar LDG B path) — used for inGEMM ----------------
template <int NT>
__global__ __launch_bounds__(128) void gemm_bf16x3(
    const unsigned* __restrict__ Ah, const unsigned* __restrict__ Al,
    const float* __restrict__ W, float* __restrict__ C,
    const float* __restrict__ bias1, const float* __restrict__ bias2,
    int N, int ldc) {
    constexpr int BN = NT * 32;
    __shared__ unsigned sAh[64][12];
    __shared__ unsigned sAl[64][12];
    __shared__ unsigned sBh[BN][12];
    __shared__ unsigned sBl[BN][12];

    const int tid = threadIdx.x;
    const int wid = tid >> 5;
    const int lane = tid & 31;
    const int l4 = lane >> 2;
    const int lq = lane & 3;
    const int n_block = blockIdx.x * BN;

    float d[4][NT][4];
#pragma unroll
    for (int mt = 0; mt < 4; mt++)
#pragma unroll
        for (int nt = 0; nt < NT; nt++)
#pragma unroll
            for (int q = 0; q < 4; q++) d[mt][nt][q] = 0.f;

    const int ar = tid >> 1;
    const int aseg = (tid & 1) * 4;

    const uint32_t aOff = (uint32_t)((lane & 15) * 48 + (lane >> 4) * 16);
    const uint32_t bOff = (uint32_t)(
        (wid * (NT * 8) + ((lane >> 4) * 8) + (lane & 7)) * 48 +
        ((lane >> 3) & 1) * 16);
    const uint32_t baseAh = smem_u32(&sAh[0][0]);
    const uint32_t baseAl = smem_u32(&sAl[0][0]);
    const uint32_t baseBh = smem_u32(&sBh[0][0]);
    const uint32_t baseBl = smem_u32(&sBl[0][0]);

    uint4 pah = *(const uint4*)(Ah + (size_t)ar * 512 + aseg);
    uint4 pal = *(const uint4*)(Al + (size_t)ar * 512 + aseg);
    float4 pb[NT];
#pragma unroll
    for (int s = 0; s < NT; s++) {
        int i = s * 128 + tid;
        int row = i >> 2, q = i & 3;
        int gn = n_block + row;
        pb[s] = make_float4(0.f, 0.f, 0.f, 0.f);
        if (gn < N) pb[s] = *(const float4*)(W + (size_t)gn * 1024 + q * 4);
    }

    for (int kt = 0; kt < 64; kt++) {
        *(uint4*)&sAh[ar][aseg] = pah;
        *(uint4*)&sAl[ar][aseg] = pal;
#pragma unroll
        for (int s = 0; s < NT; s++) {
            int i = s * 128 + tid;
            int row = i >> 2, q = i & 3;
            unsigned h0, l0, h1, l1;
            cvt_pair(pb[s].x, pb[s].y, h0, l0);
            cvt_pair(pb[s].z, pb[s].w, h1, l1);
            sBh[row][q * 2] = h0;
            sBh[row][q * 2 + 1] = h1;
            sBl[row][q * 2] = l0;
            sBl[row][q * 2 + 1] = l1;
        }
        __syncthreads();

        if (kt + 1 < 64) {
            const int kp = (kt + 1) * 16;
            pah = *(const uint4*)(Ah + (size_t)ar * 512 + (kt + 1) * 8 + aseg);
            pal = *(const uint4*)(Al + (size_t)ar * 512 + (kt + 1) * 8 + aseg);
#pragma unroll
            for (int s = 0; s < NT; s++) {
                int i = s * 128 + tid;
                int row = i >> 2, q = i & 3;
                int gn = n_block + row;
                pb[s] = make_float4(0.f, 0.f, 0.f, 0.f);
                if (gn < N) pb[s] = *(const float4*)(W + (size_t)gn * 1024 + kp + q * 4);
            }
        }

        {
            unsigned bh[NT][2], bl[NT][2];
#pragma unroll
            for (int p = 0; p < NT / 2; p++) {
                uint32_t off = bOff + (uint32_t)(p * 768);
                ldsm_x4(bh[2 * p][0], bh[2 * p][1], bh[2 * p + 1][0],
                        bh[2 * p + 1][1], baseBh + off);
                ldsm_x4(bl[2 * p][0], bl[2 * p][1], bl[2 * p + 1][0],
                        bl[2 * p + 1][1], baseBl + off);
            }
#pragma unroll
            for (int mt = 0; mt < 4; mt++) {
                uint32_t off = aOff + (uint32_t)(mt * 768);
                unsigned ah[4], al[4];
                ldsm_x4(ah[0], ah[1], ah[2], ah[3], baseAh + off);
                ldsm_x4(al[0], al[1], al[2], al[3], baseAl + off);
#pragma unroll
                for (int nt = 0; nt < NT; nt++) {
                    mma_bf16(d[mt][nt], ah, bh[nt]);
                    mma_bf16(d[mt][nt], ah, bl[nt]);
                    mma_bf16(d[mt][nt], al, bh[nt]);
                }
            }
        }
        __syncthreads();
    }

#pragma unroll
    for (int mt = 0; mt < 4; mt++) {
        int row0 = mt * 16 + l4;
#pragma unroll
        for (int nt = 0; nt < NT; nt++) {
            int col0 = n_block + wid * (NT * 8) + nt * 8 + lq * 2;
#pragma unroll
            for (int half = 0; half < 2; half++) {
                int row = row0 + half * 8;
                if (row < 50) {
                    float* crow = C + (size_t)row * ldc;
                    if (col0 < N) {
                        float bv = bias1[col0] + (bias2 ? bias2[col0] : 0.f);
                        crow[col0] = d[mt][nt][half * 2 + 0] + bv;
                    }
                    if (col0 + 1 < N) {
                        float bv = bias1[col0 + 1] + (bias2 ? bias2[col0 + 1] : 0.f);
                        crow[col0 + 1] = d[mt][nt][half * 2 + 1] + bv;
                    }
                }
            }
        }
    }
}

// ---------------- R15-measured GEMM (cp.async B pipeline) — used for outGEMM ----------------
template <int NT>
__global__ __launch_bounds__(128) void gemm_bf16x3_cp(
    const unsigned* __restrict__ Ah, const unsigned* __restrict__ Al,
    const float* __restrict__ W, float* __restrict__ C,
    const float* __restrict__ bias1, const float* __restrict__ bias2,
    int N, int ldc) {
    constexpr int BN = NT * 32;
    constexpr int RAWP = 20;
    __shared__ unsigned sAh[64][12];
    __shared__ unsigned sAl[64][12];
    __shared__ unsigned sBh[BN][12];
    __shared__ unsigned sBl[BN][12];
    __shared__ __align__(16) float rawB[2][BN * RAWP];

    const int tid = threadIdx.x;
    const int wid = tid >> 5;
    const int lane = tid & 31;
    const int l4 = lane >> 2;
    const int lq = lane & 3;
    const int n_block = blockIdx.x * BN;

    float d[4][NT][4];
#pragma unroll
    for (int mt = 0; mt < 4; mt++)
#pragma unroll
        for (int nt = 0; nt < NT; nt++)
#pragma unroll
            for (int q = 0; q < 4; q++) d[mt][nt][q] = 0.f;

    const int ar = tid >> 1;
    const int aseg = (tid & 1) * 4;

    int brow[NT], bq[NT];
    const float* bsrc[NT];
    unsigned bsz[NT];
#pragma unroll
    for (int s = 0; s < NT; s++) {
        int j = tid * NT + s;
        brow[s] = j >> 2;
        bq[s] = j & 3;
        int gn = n_block + brow[s];
        bool ok = (gn < N);
        bsrc[s] = W + (size_t)(ok ? gn : 0) * 1024 + bq[s] * 4;
        bsz[s] = ok ? 16u : 0u;
    }
    const uint32_t rawBase = smem_u32(&rawB[0][0]);

    const uint32_t aOff = (uint32_t)((lane & 15) * 48 + (lane >> 4) * 16);
    const uint32_t bOff = (uint32_t)(
        (wid * (NT * 8) + ((lane >> 4) * 8) + (lane & 7)) * 48 +
        ((lane >> 3) & 1) * 16);
    const uint32_t baseAh = smem_u32(&sAh[0][0]);
    const uint32_t baseAl = smem_u32(&sAl[0][0]);
    const uint32_t baseBh = smem_u32(&sBh[0][0]);
    const uint32_t baseBl = smem_u32(&sBl[0][0]);

#pragma unroll
    for (int p = 0; p < 2; p++) {
#pragma unroll
        for (int s = 0; s < NT; s++) {
            uint32_t dst = rawBase +
                (uint32_t)((p * BN * RAWP + brow[s] * RAWP + bq[s] * 4) * 4);
            cp_async16(dst, bsrc[s] + p * 16, bsz[s]);
        }
        cp_commit();
    }
    uint4 pah = *(const uint4*)(Ah + (size_t)ar * 512 + aseg);
    uint4 pal = *(const uint4*)(Al + (size_t)ar * 512 + aseg);

    for (int kt = 0; kt < 64; kt++) {
        const int slot = kt & 1;
        cp_wait1();
        __syncthreads();

        *(uint4*)&sAh[ar][aseg] = pah;
        *(uint4*)&sAl[ar][aseg] = pal;
#pragma unroll
        for (int s = 0; s < NT; s++) {
            float4 v = *(const float4*)&rawB[slot][brow[s] * RAWP + bq[s] * 4];
            unsigned h0, l0, h1, l1;
            cvt_pair(v.x, v.y, h0, l0);
            cvt_pair(v.z, v.w, h1, l1);
            *(uint2*)&sBh[brow[s]][bq[s] * 2] = make_uint2(h0, h1);
            *(uint2*)&sBl[brow[s]][bq[s] * 2] = make_uint2(l0, l1);
        }
        __syncthreads();

        if (kt + 2 < 64) {
#pragma unroll
            for (int s = 0; s < NT; s++) {
                uint32_t dst = rawBase +
                    (uint32_t)((slot * BN * RAWP + brow[s] * RAWP + bq[s] * 4) * 4);
                cp_async16(dst, bsrc[s] + (kt + 2) * 16, bsz[s]);
            }
        }
        cp_commit();
        if (kt + 1 < 64) {
            pah = *(const uint4*)(Ah + (size_t)ar * 512 + (kt + 1) * 8 + aseg);
            pal = *(const uint4*)(Al + (size_t)ar * 512 + (kt + 1) * 8 + aseg);
        }

        {
            unsigned bh[NT][2], bl[NT][2];
#pragma unroll
            for (int p = 0; p < NT / 2; p++) {
                uint32_t off = bOff + (uint32_t)(p * 768);
                ldsm_x4(bh[2 * p][0], bh[2 * p][1], bh[2 * p + 1][0],
                        bh[2 * p + 1][1], baseBh + off);
                ldsm_x4(bl[2 * p][0], bl[2 * p][1], bl[2 * p + 1][0],
                        bl[2 * p + 1][1], baseBl + off);
            }
#pragma unroll
            for (int mt = 0; mt < 4; mt++) {
                uint32_t off = aOff + (uint32_t)(mt * 768);
                unsigned ah[4], al[4];
                ldsm_x4(ah[0], ah[1], ah[2], ah[3], baseAh + off);
                ldsm_x4(al[0], al[1], al[2], al[3], baseAl + off);
#pragma unroll
                for (int nt = 0; nt < NT; nt++) {
                    mma_bf16(d[mt][nt], ah, bh[nt]);
                    mma_bf16(d[mt][nt], ah, bl[nt]);
                    mma_bf16(d[mt][nt], al, bh[nt]);
                }
            }
        }
    }

#pragma unroll
    for (int mt = 0; mt < 4; mt++) {
        int row0 = mt * 16 + l4;
#pragma unroll
        for (int nt = 0; nt < NT; nt++) {
            int col0 = n_block + wid * (NT * 8) + nt * 8 + lq * 2;
#pragma unroll
            for (int half = 0; half < 2; half++) {
                int row = row0 + half * 8;
                if (row < 50) {
                    float* crow = C + (size_t)row * ldc;
                    if (col0 < N) {
                        float bv = bias1[col0] + (bias2 ? bias2[col0] : 0.f);
                        crow[col0] = d[mt][nt][half * 2 + 0] + bv;
                    }
                    if (col0 + 1 < N) {
                        float bv = bias1[col0 + 1] + (bias2 ? bias2[col0 + 1] : 0.f);
                        crow[col0 + 1] = d[mt][nt][half * 2 + 1] + bv;
                    }
                }
            }
        }
    }
}

// ---------------- persistent LSTM (R14-proven, byte-identical) ----------------
__global__ __launch_bounds__(256, 1) void lstm_persistent(
    const float* __restrict__ Whh,      // [4096][1024]
    const float* __restrict__ gin_all,  // [50][4096]
    const float* __restrict__ c0) {     // [1024]
    const int b = blockIdx.x;
    const int tid = threadIdx.x;
    const int w = tid >> 5;              // warp -> unit b*8+w
    const int lane = tid & 31;
    const int r = lane >> 3;             // gate 0..3
    const int c = lane & 7;              // chunk 0..7
    const int u = b * 8 + w;
    const int grow = r * 1024 + u;

    __shared__ __align__(16) ull h_q[512];
    __shared__ float sGin[NSTEP][4][8];

    if (tid < 200) {
        int t = tid >> 2, g = tid & 3;
        const float4* src = (const float4*)(gin_all + (size_t)t * 4096 + g * 1024 + b * 8);
        ((float4*)&sGin[t][g][0])[0] = src[0];
        ((float4*)&sGin[t][g][0])[1] = src[1];
    }
    float cc = 0.f;
    if (lane == 0) cc = c0[u];

    ull Wq[64];
    const float4* wp = (const float4*)(Whh + (size_t)grow * 1024);
#pragma unroll
    for (int it = 0; it < 32; it++) {
        float4 w4 = wp[it * 8 + c];
        Wq[2 * it + 0] = pack2(w4.x, w4.y);
        Wq[2 * it + 1] = pack2(w4.z, w4.w);
    }
    __syncthreads();

    for (int t = 0; t < NSTEP; t++) {
        {
            float4 hv = ((const float4*)g_h[t & 1])[tid];
            ulonglong2 hq;
            hq.x = pack2(hv.x, hv.y);
            hq.y = pack2(hv.z, hv.w);
            *((ulonglong2*)&h_q[2 * tid]) = hq;
        }
        __syncthreads();

        ull a0 = 0, a1 = 0;
#pragma unroll
        for (int it = 0; it < 32; it++) {
            ulonglong2 hq = *(const ulonglong2*)&h_q[it * 16 + c * 2];
            ffma2(a0, Wq[2 * it + 0], hq.x);
            ffma2(a1, Wq[2 * it + 1], hq.y);
        }
        float sum = sum2(a0) + sum2(a1);
        sum += __shfl_xor_sync(0xFFFFFFFFu, sum, 1);
        sum += __shfl_xor_sync(0xFFFFFFFFu, sum, 2);
        sum += __shfl_xor_sync(0xFFFFFFFFu, sum, 4);
        sum += sGin[t][r][w];

        float vi = __shfl_sync(0xFFFFFFFFu, sum, 0);
        float vf = __shfl_sync(0xFFFFFFFFu, sum, 8);
        float vg = __shfl_sync(0xFFFFFFFFu, sum, 16);
        float vo = __shfl_sync(0xFFFFFFFFu, sum, 24);

        if (lane == 0) {
            float ig = __fdividef(1.f, 1.f + __expf(-vi));
            float fg = __fdividef(1.f, 1.f + __expf(-vf));
            float gg = 1.f - __fdividef(2.f, __expf(2.f * vg) + 1.f);
            float og = __fdividef(1.f, 1.f + __expf(-vo));
            float cn = fg * cc + ig * gg;
            cc = cn;
            float hn = og * (1.f - __fdividef(2.f, __expf(2.f * cn) + 1.f));
            g_h[(t + 1) & 1][u] = hn;
            g_HS[(size_t)t * 1024 + u] = hn;
        }
        __syncthreads();

        if (tid == 0) {
            red_release_add1(&g_arrive);
            const unsigned target = (unsigned)NBLK * (unsigned)(t + 1);
            while (ld_acquire(&g_arrive) < target) {}
        }
        __syncthreads();
    }
}

// ---------------- launch ----------------
extern "C" void kernel_launch(void* const* d_in, const int* in_sizes, int n_in,
                              void* d_out, int out_size) {
    const int* sent = (const int*)d_in[0];
    const float* h0 = (const float*)d_in[1];
    const float* c0 = (const float*)d_in[2];
    const float* emb = (const float*)d_in[3];
    const float* Wih = (const float*)d_in[4];
    const float* Whh = (const float*)d_in[5];
    const float* bih = (const float*)d_in[6];
    const float* bhh = (const float*)d_in[7];
    const float* Wout = (const float*)d_in[8];
    const float* bout = (const float*)d_in[9];
    float* out = (float*)d_out;

    float* gX;
    float* gGin;
    float* gHS;
    unsigned* gAh;
    unsigned* gAl;
    cudaGetSymbolAddress((void**)&gX, g_X);
    cudaGetSymbolAddress((void**)&gGin, g_Gin);
    cudaGetSymbolAddress((void**)&gHS, g_HS);
    cudaGetSymbolAddress((void**)&gAh, g_Ah);
    cudaGetSymbolAddress((void**)&gAl, g_Al);

    // 1) gather inputs + init state + reset barrier
    prep_kernel<<<65, 256>>>(sent, emb, h0);

    // 2) input projection: Gin = X @ W_ih^T + (b_ih + b_hh)   [R14 scalar path]
    cvt_split_kernel<<<128, 256>>>(gX);
    gemm_bf16x3<2><<<4096 / 64, 128>>>(gAh, gAl, Wih, gGin, bih, bhh, 4096, 4096);

    // 3) persistent recurrence (register-resident W_hh, counter barrier)
    lstm_persistent<<<NBLK, 256>>>(Whh, gGin, c0);

    // 4) output projection: logits = HS @ W_out^T + b_out     [cp.async path]
    cvt_split_kernel<<<128, 256>>>(gHS);
    gemm_bf16x3_cp<4><<<(NOUT + 127) / 128, 128>>>(gAh, gAl, Wout, out, bout,
                                                   nullptr, NOUT, NOUT);
}

// round 17
// speedup vs baseline: 1.2376x; 1.2376x over previous
#include <cuda_runtime.h>
#include <cuda_bf16.h>
#include <math.h>
#include <stdint.h>

typedef unsigned long long ull;

#define NBLK 128
#define NSTEP 50
#define NOUT 50257

// ---------------- device scratch (no allocs allowed) ----------------
__device__ float g_Gin[50 * 4096];    // W_ih @ x_t + b_ih + b_hh
__device__ float g_HS[64 * 1024];     // h_t history (rows 50..63 zero)
__device__ float g_h[2][1024];        // double-buffered hidden state
__device__ unsigned g_arrive;         // cumulative grid-barrier counter
__device__ __align__(16) unsigned g_Ah[64 * 512];  // A bf16-hi pairs (X or HS)
__device__ __align__(16) unsigned g_Al[64 * 512];  // A bf16-lo pairs
__device__ float g_P[4 * 64 * 4096];  // split-K partials for inGEMM

// ---------------- helpers ----------------
__device__ __forceinline__ ull pack2(float x, float y) {
    ull r;
    asm("mov.b64 %0, {%1, %2};" : "=l"(r) : "f"(x), "f"(y));
    return r;
}
__device__ __forceinline__ void ffma2(ull& d, ull a, ull b) {
    asm("fma.rn.f32x2 %0, %1, %2, %0;" : "+l"(d) : "l"(a), "l"(b));
}
__device__ __forceinline__ float sum2(ull a) {
    float2 v = *(float2*)&a;
    return v.x + v.y;
}
__device__ __forceinline__ void red_release_add1(unsigned* p) {
    asm volatile("red.release.gpu.global.add.u32 [%0], 1;" :: "l"(p) : "memory");
}
__device__ __forceinline__ unsigned ld_acquire(const unsigned* p) {
    unsigned v;
    asm volatile("ld.acquire.gpu.global.u32 %0, [%1];" : "=r"(v) : "l"(p) : "memory");
    return v;
}
__device__ __forceinline__ uint32_t smem_u32(const void* p) {
    uint32_t a;
    asm("{ .reg .u64 t; cvta.to.shared.u64 t, %1; cvt.u32.u64 %0, t; }"
        : "=r"(a) : "l"(p));
    return a;
}
// ldmatrix x4: four 8x8 b16 tiles (baseline PTX, sm_75+)
__device__ __forceinline__ void ldsm_x4(unsigned& r0, unsigned& r1, unsigned& r2,
                                        unsigned& r3, uint32_t addr) {
    asm volatile(
        "ldmatrix.sync.aligned.m8n8.x4.shared.b16 {%0,%1,%2,%3}, [%4];"
        : "=r"(r0), "=r"(r1), "=r"(r2), "=r"(r3) : "r"(addr));
}

// bf16 hi/lo split of a float pair, packed little-endian (x=low half)
__device__ __forceinline__ void cvt_pair(float x, float y, unsigned& hi, unsigned& lo) {
    __nv_bfloat162 h = __floats2bfloat162_rn(x, y);
    float rx = x - __bfloat162float(h.x);
    float ry = y - __bfloat162float(h.y);
    __nv_bfloat162 l = __floats2bfloat162_rn(rx, ry);
    hi = *(unsigned*)&h;
    lo = *(unsigned*)&l;
}

// mma.sync m16n8k16 bf16 (baseline PTX, works on compute_100)
__device__ __forceinline__ void mma_bf16(float* d, const unsigned* a, const unsigned* b) {
    asm volatile(
        "mma.sync.aligned.m16n8k16.row.col.f32.bf16.bf16.f32 "
        "{%0,%1,%2,%3}, {%4,%5,%6,%7}, {%8,%9}, {%0,%1,%2,%3};"
        : "+f"(d[0]), "+f"(d[1]), "+f"(d[2]), "+f"(d[3])
        : "r"(a[0]), "r"(a[1]), "r"(a[2]), "r"(a[3]), "r"(b[0]), "r"(b[1]));
}

// ---------------- prep: gather X rows -> bf16 hi/lo A-bufs, zero pads, init ----------------
__global__ void prep_kernel(const int* __restrict__ sent,
                            const float* __restrict__ emb,
                            const float* __restrict__ h0) {
    int b = blockIdx.x;
    int tid = threadIdx.x;  // 256 threads
    if (b < 64) {
        float4 v = make_float4(0.f, 0.f, 0.f, 0.f);
        if (b < 50) {
            int row = (b == 0) ? 1 : sent[b - 1];  // START_ID = 1
            v = ((const float4*)(emb + (size_t)row * 1024))[tid];
        } else {
            // zero MMA pad rows of the HS buffer (read by cvt_split later)
            ((float4*)(g_HS + (size_t)b * 1024))[tid] = v;
        }
        unsigned h0w, l0w, h1w, l1w;
        cvt_pair(v.x, v.y, h0w, l0w);
        cvt_pair(v.z, v.w, h1w, l1w);
        *(uint2*)&g_Ah[(size_t)b * 512 + tid * 2] = make_uint2(h0w, h1w);
        *(uint2*)&g_Al[(size_t)b * 512 + tid * 2] = make_uint2(l0w, l1w);
    } else {
        ((float4*)g_h[0])[tid] = ((const float4*)h0)[tid];
        if (tid == 0) g_arrive = 0u;
    }
}

// ---------------- split a fp32 [64][1024] matrix into packed bf16 hi/lo ----------------
__global__ void cvt_split_kernel(const float* __restrict__ src) {
    int i = blockIdx.x * 256 + threadIdx.x;  // over 32768 float2 pairs
    float2 v = ((const float2*)src)[i];
    unsigned hi, lo;
    cvt_pair(v.x, v.y, hi, lo);
    g_Ah[i] = hi;
    g_Al[i] = lo;
}

// ---------------- bf16x3 tensor-core GEMM (R14-proven) with k-tile range ----------------
// A: precomputed hi/lo packed bf16 pairs [64][512]. W: [N][1024] fp32 row-major.
// CTA: BM=64, BN=NT*32, 4 warps. Processes nkt k-tiles starting at blockIdx.y*nkt.
// Output row base: C + blockIdx.y * 64 * ldc (split-K partials; y=0 for full-K).
// 3-term bf16 split: D += Ah*Bh + Ah*Bl + Al*Bh.
template <int NT>
__global__ __launch_bounds__(128) void gemm_bf16x3(
    const unsigned* __restrict__ Ah, const unsigned* __restrict__ Al,
    const float* __restrict__ W, float* __restrict__ C,
    const float* __restrict__ bias1, const float* __restrict__ bias2,
    int N, int ldc, int nkt) {
    constexpr int BN = NT * 32;
    __shared__ unsigned sAh[64][12];
    __shared__ unsigned sAl[64][12];
    __shared__ unsigned sBh[BN][12];
    __shared__ unsigned sBl[BN][12];

    const int tid = threadIdx.x;
    const int wid = tid >> 5;
    const int lane = tid & 31;
    const int l4 = lane >> 2;
    const int lq = lane & 3;
    const int n_block = blockIdx.x * BN;
    const int kt0 = blockIdx.y * nkt;     // global k-tile base
    float* Cp = C + (size_t)blockIdx.y * 64 * ldc;

    float d[4][NT][4];
#pragma unroll
    for (int mt = 0; mt < 4; mt++)
#pragma unroll
        for (int nt = 0; nt < NT; nt++)
#pragma unroll
            for (int q = 0; q < 4; q++) d[mt][nt][q] = 0.f;

    const int ar = tid >> 1;
    const int aseg = (tid & 1) * 4;

    const uint32_t aOff = (uint32_t)((lane & 15) * 48 + (lane >> 4) * 16);
    const uint32_t bOff = (uint32_t)(
        (wid * (NT * 8) + ((lane >> 4) * 8) + (lane & 7)) * 48 +
        ((lane >> 3) & 1) * 16);
    const uint32_t baseAh = smem_u32(&sAh[0][0]);
    const uint32_t baseAl = smem_u32(&sAl[0][0]);
    const uint32_t baseBh = smem_u32(&sBh[0][0]);
    const uint32_t baseBl = smem_u32(&sBl[0][0]);

    uint4 pah = *(const uint4*)(Ah + (size_t)ar * 512 + kt0 * 8 + aseg);
    uint4 pal = *(const uint4*)(Al + (size_t)ar * 512 + kt0 * 8 + aseg);
    float4 pb[NT];
#pragma unroll
    for (int s = 0; s < NT; s++) {
        int i = s * 128 + tid;
        int row = i >> 2, q = i & 3;
        int gn = n_block + row;
        pb[s] = make_float4(0.f, 0.f, 0.f, 0.f);
        if (gn < N) pb[s] = *(const float4*)(W + (size_t)gn * 1024 + kt0 * 16 + q * 4);
    }

    for (int kt = 0; kt < nkt; kt++) {
        *(uint4*)&sAh[ar][aseg] = pah;
        *(uint4*)&sAl[ar][aseg] = pal;
#pragma unroll
        for (int s = 0; s < NT; s++) {
            int i = s * 128 + tid;
            int row = i >> 2, q = i & 3;
            unsigned h0, l0, h1, l1;
            cvt_pair(pb[s].x, pb[s].y, h0, l0);
            cvt_pair(pb[s].z, pb[s].w, h1, l1);
            sBh[row][q * 2] = h0;
            sBh[row][q * 2 + 1] = h1;
            sBl[row][q * 2] = l0;
            sBl[row][q * 2 + 1] = l1;
        }
        __syncthreads();

        if (kt + 1 < nkt) {
            const int g = kt0 + kt + 1;
            pah = *(const uint4*)(Ah + (size_t)ar * 512 + g * 8 + aseg);
            pal = *(const uint4*)(Al + (size_t)ar * 512 + g * 8 + aseg);
#pragma unroll
            for (int s = 0; s < NT; s++) {
                int i = s * 128 + tid;
                int row = i >> 2, q = i & 3;
                int gn = n_block + row;
                pb[s] = make_float4(0.f, 0.f, 0.f, 0.f);
                if (gn < N)
                    pb[s] = *(const float4*)(W + (size_t)gn * 1024 + g * 16 + q * 4);
            }
        }

        {
            unsigned bh[NT][2], bl[NT][2];
#pragma unroll
            for (int p = 0; p < NT / 2; p++) {
                uint32_t off = bOff + (uint32_t)(p * 768);
                ldsm_x4(bh[2 * p][0], bh[2 * p][1], bh[2 * p + 1][0],
                        bh[2 * p + 1][1], baseBh + off);
                ldsm_x4(bl[2 * p][0], bl[2 * p][1], bl[2 * p + 1][0],
                        bl[2 * p + 1][1], baseBl + off);
            }
#pragma unroll
            for (int mt = 0; mt < 4; mt++) {
                uint32_t off = aOff + (uint32_t)(mt * 768);
                unsigned ah[4], al[4];
                ldsm_x4(ah[0], ah[1], ah[2], ah[3], baseAh + off);
                ldsm_x4(al[0], al[1], al[2], al[3], baseAl + off);
#pragma unroll
                for (int nt = 0; nt < NT; nt++) {
                    mma_bf16(d[mt][nt], ah, bh[nt]);
                    mma_bf16(d[mt][nt], ah, bl[nt]);
                    mma_bf16(d[mt][nt], al, bh[nt]);
                }
            }
        }
        __syncthreads();
    }

    // epilogue: d[mt][nt] -> rows m<50, cols<N, + optional biases
#pragma unroll
    for (int mt = 0; mt < 4; mt++) {
        int row0 = mt * 16 + l4;
#pragma unroll
        for (int nt = 0; nt < NT; nt++) {
            int col0 = n_block + wid * (NT * 8) + nt * 8 + lq * 2;
#pragma unroll
            for (int half = 0; half < 2; half++) {
                int row = row0 + half * 8;
                if (row < 50) {
                    float* crow = Cp + (size_t)row * ldc;
                    if (col0 < N) {
                        float bv = (bias1 ? bias1[col0] : 0.f) +
                                   (bias2 ? bias2[col0] : 0.f);
                        crow[col0] = d[mt][nt][half * 2 + 0] + bv;
                    }
                    if (col0 + 1 < N) {
                        float bv = (bias1 ? bias1[col0 + 1] : 0.f) +
                                   (bias2 ? bias2[col0 + 1] : 0.f);
                        crow[col0 + 1] = d[mt][nt][half * 2 + 1] + bv;
                    }
                }
            }
        }
    }
}

// ---------------- combine: Gin = P0+P1+P2+P3 + bih + bhh (R7-proven) ----------------
__global__ void combine_gin_kernel(const float* __restrict__ bih,
                                   const float* __restrict__ bhh) {
    int m = blockIdx.y;
    int n = blockIdx.x * 256 + threadIdx.x;
    float s = bih[n] + bhh[n];
#pragma unroll
    for (int sp = 0; sp < 4; sp++)
        s += g_P[(size_t)sp * 64 * 4096 + (size_t)m * 4096 + n];
    g_Gin[(size_t)m * 4096 + n] = s;
}

// ---------------- persistent LSTM (R14-proven, byte-identical) ----------------
__global__ __launch_bounds__(256, 1) void lstm_persistent(
    const float* __restrict__ Whh,      // [4096][1024]
    const float* __restrict__ gin_all,  // [50][4096]
    const float* __restrict__ c0) {     // [1024]
    const int b = blockIdx.x;
    const int tid = threadIdx.x;
    const int w = tid >> 5;              // warp -> unit b*8+w
    const int lane = tid & 31;
    const int r = lane >> 3;             // gate 0..3
    const int c = lane & 7;              // chunk 0..7
    const int u = b * 8 + w;
    const int grow = r * 1024 + u;

    __shared__ __align__(16) ull h_q[512];
    __shared__ float sGin[NSTEP][4][8];

    if (tid < 200) {
        int t = tid >> 2, g = tid & 3;
        const float4* src = (const float4*)(gin_all + (size_t)t * 4096 + g * 1024 + b * 8);
        ((float4*)&sGin[t][g][0])[0] = src[0];
        ((float4*)&sGin[t][g][0])[1] = src[1];
    }
    float cc = 0.f;
    if (lane == 0) cc = c0[u];

    ull Wq[64];
    const float4* wp = (const float4*)(Whh + (size_t)grow * 1024);
#pragma unroll
    for (int it = 0; it < 32; it++) {
        float4 w4 = wp[it * 8 + c];
        Wq[2 * it + 0] = pack2(w4.x, w4.y);
        Wq[2 * it + 1] = pack2(w4.z, w4.w);
    }
    __syncthreads();

    for (int t = 0; t < NSTEP; t++) {
        {
            float4 hv = ((const float4*)g_h[t & 1])[tid];
            ulonglong2 hq;
            hq.x = pack2(hv.x, hv.y);
            hq.y = pack2(hv.z, hv.w);
            *((ulonglong2*)&h_q[2 * tid]) = hq;
        }
        __syncthreads();

        ull a0 = 0, a1 = 0;
#pragma unroll
        for (int it = 0; it < 32; it++) {
            ulonglong2 hq = *(const ulonglong2*)&h_q[it * 16 + c * 2];
            ffma2(a0, Wq[2 * it + 0], hq.x);
            ffma2(a1, Wq[2 * it + 1], hq.y);
        }
        float sum = sum2(a0) + sum2(a1);
        sum += __shfl_xor_sync(0xFFFFFFFFu, sum, 1);
        sum += __shfl_xor_sync(0xFFFFFFFFu, sum, 2);
        sum += __shfl_xor_sync(0xFFFFFFFFu, sum, 4);
        sum += sGin[t][r][w];

        float vi = __shfl_sync(0xFFFFFFFFu, sum, 0);
        float vf = __shfl_sync(0xFFFFFFFFu, sum, 8);
        float vg = __shfl_sync(0xFFFFFFFFu, sum, 16);
        float vo = __shfl_sync(0xFFFFFFFFu, sum, 24);

        if (lane == 0) {
            float ig = __fdividef(1.f, 1.f + __expf(-vi));
            float fg = __fdividef(1.f, 1.f + __expf(-vf));
            float gg = 1.f - __fdividef(2.f, __expf(2.f * vg) + 1.f);
            float og = __fdividef(1.f, 1.f + __expf(-vo));
            float cn = fg * cc + ig * gg;
            cc = cn;
            float hn = og * (1.f - __fdividef(2.f, __expf(2.f * cn) + 1.f));
            g_h[(t + 1) & 1][u] = hn;
            g_HS[(size_t)t * 1024 + u] = hn;
        }
        __syncthreads();

        if (tid == 0) {
            red_release_add1(&g_arrive);
            const unsigned target = (unsigned)NBLK * (unsigned)(t + 1);
            while (ld_acquire(&g_arrive) < target) {}
        }
        __syncthreads();
    }
}

// ---------------- launch ----------------
extern "C" void kernel_launch(void* const* d_in, const int* in_sizes, int n_in,
                              void* d_out, int out_size) {
    const int* sent = (const int*)d_in[0];
    const float* h0 = (const float*)d_in[1];
    const float* c0 = (const float*)d_in[2];
    const float* emb = (const float*)d_in[3];
    const float* Wih = (const float*)d_in[4];
    const float* Whh = (const float*)d_in[5];
    const float* bih = (const float*)d_in[6];
    const float* bhh = (const float*)d_in[7];
    const float* Wout = (const float*)d_in[8];
    const float* bout = (const float*)d_in[9];
    float* out = (float*)d_out;

    float* gGin;
    float* gHS;
    unsigned* gAh;
    unsigned* gAl;
    float* gP;
    cudaGetSymbolAddress((void**)&gGin, g_Gin);
    cudaGetSymbolAddress((void**)&gHS, g_HS);
    cudaGetSymbolAddress((void**)&gAh, g_Ah);
    cudaGetSymbolAddress((void**)&gAl, g_Al);
    cudaGetSymbolAddress((void**)&gP, g_P);

    // 1) gather inputs -> bf16 hi/lo A-bufs + init state + reset barrier
    prep_kernel<<<65, 256>>>(sent, emb, h0);

    // 2) input projection, split-K=4: partials then combine (+ biases)
    {
        dim3 grid(4096 / 64, 4);
        gemm_bf16x3<2><<<grid, 128>>>(gAh, gAl, Wih, gP, nullptr, nullptr,
                                      4096, 4096, 16);
        dim3 cgrid(4096 / 256, 50);
        combine_gin_kernel<<<cgrid, 256>>>(bih, bhh);
    }

    // 3) persistent recurrence (register-resident W_hh, counter barrier)
    lstm_persistent<<<NBLK, 256>>>(Whh, gGin, c0);

    // 4) output projection: logits = HS @ W_out^T + b_out
    cvt_split_kernel<<<128, 256>>>(gHS);
    {
        dim3 grid((NOUT + 127) / 128, 1);
        gemm_bf16x3<4><<<grid, 128>>>(gAh, gAl, Wout, out, bout, nullptr,
                                      NOUT, NOUT, 64);
    }
}